// round 1
// baseline (speedup 1.0000x reference)
#include <cuda_runtime.h>
#include <cuda_bf16.h>
#include <cstdint>

// Problem constants (LocalAttentionPairBias: D=1, L=4096, c=128, H=4, dh=32, k=128, c_pair=16)
constexpr int L   = 4096;
constexpr int C   = 128;
constexpr int H   = 4;
constexpr int DH  = 32;
constexpr int KNN = 128;
constexpr int CP  = 16;

// Scratch (device globals — no allocation allowed)
__device__ float g_a [L * C];
__device__ float g_q [L * C];
__device__ float g_k [L * C];
__device__ float g_v [L * C];
__device__ float g_g [L * C];
__device__ float g_ao[L * C];

// ---------------------------------------------------------------------------
// RMSNorm: one 128-thread block per row of 128
// ---------------------------------------------------------------------------
__global__ void __launch_bounds__(128) rms_kernel(const float* __restrict__ x,
                                                  const float* __restrict__ w,
                                                  float* __restrict__ y) {
    int row = blockIdx.x;
    int t = threadIdx.x;
    float v = x[(size_t)row * C + t];
    float s = v * v;
    #pragma unroll
    for (int o = 16; o; o >>= 1) s += __shfl_xor_sync(0xffffffffu, s, o);
    __shared__ float ws[4];
    if ((t & 31) == 0) ws[t >> 5] = s;
    __syncthreads();
    float tot = ws[0] + ws[1] + ws[2] + ws[3];
    float r = rsqrtf(tot * (1.0f / C) + 1e-5f);
    y[(size_t)row * C + t] = v * r * w[t];
}

// ---------------------------------------------------------------------------
// GEMM  C[m][n] = sum_k A[m][k] * W[n][k]   (K = 128, BN = 64, BK = 32)
// Handles up to 4 weight matrices (blockIdx.y selects matrix + column half).
// Optional sigmoid epilogue on one matrix.
// ---------------------------------------------------------------------------
template <int BM>
__global__ void __launch_bounds__(256) gemm_nt_kernel(
    const float* __restrict__ A,
    const float* __restrict__ W0, const float* __restrict__ W1,
    const float* __restrict__ W2, const float* __restrict__ W3,
    float* __restrict__ C0, float* __restrict__ C1,
    float* __restrict__ C2, float* __restrict__ C3,
    int tilesPerMat, int sigmoidMat) {
    constexpr int BN = 64;
    constexpr int TM = BM / 16;

    __shared__ float Asm[BM][36];   // [m][k-chunk], padded
    __shared__ float Bsm[32][68];   // [k-chunk][n], padded (transposed W)

    int ct  = blockIdx.y;
    int mat = ct / tilesPerMat;
    int sub = ct % tilesPerMat;
    const float* Wsel = (mat == 0) ? W0 : (mat == 1) ? W1 : (mat == 2) ? W2 : W3;
    const float* W = Wsel + (size_t)sub * BN * 128;
    float* Csel = (mat == 0) ? C0 : (mat == 1) ? C1 : (mat == 2) ? C2 : C3;

    int m0 = blockIdx.x * BM;
    int ty = threadIdx.x >> 4;
    int tx = threadIdx.x & 15;

    float acc[TM][4];
    #pragma unroll
    for (int i = 0; i < TM; i++)
        #pragma unroll
        for (int j = 0; j < 4; j++) acc[i][j] = 0.f;

    for (int kc = 0; kc < 4; kc++) {
        // stage A chunk: BM rows x 32 cols (coalesced float4)
        for (int idx = threadIdx.x; idx < BM * 8; idx += 256) {
            int m = idx >> 3, k4 = idx & 7;
            float4 v = *(const float4*)(A + (size_t)(m0 + m) * 128 + kc * 32 + k4 * 4);
            *(float4*)&Asm[m][k4 * 4] = v;
        }
        // stage W chunk transposed: Bsm[k][n]
        for (int idx = threadIdx.x; idx < BN * 8; idx += 256) {
            int n = idx & 63, k4 = idx >> 6;
            float4 v = *(const float4*)(W + (size_t)n * 128 + kc * 32 + k4 * 4);
            Bsm[k4 * 4 + 0][n] = v.x;
            Bsm[k4 * 4 + 1][n] = v.y;
            Bsm[k4 * 4 + 2][n] = v.z;
            Bsm[k4 * 4 + 3][n] = v.w;
        }
        __syncthreads();

        #pragma unroll
        for (int k0 = 0; k0 < 32; k0 += 4) {
            float4 a4[TM];
            #pragma unroll
            for (int i = 0; i < TM; i++)
                a4[i] = *(const float4*)&Asm[ty * TM + i][k0];
            float4 b4[4];
            #pragma unroll
            for (int dk = 0; dk < 4; dk++)
                b4[dk] = *(const float4*)&Bsm[k0 + dk][tx * 4];
            #pragma unroll
            for (int dk = 0; dk < 4; dk++) {
                #pragma unroll
                for (int i = 0; i < TM; i++) {
                    float av = (&a4[i].x)[dk];
                    acc[i][0] = fmaf(av, b4[dk].x, acc[i][0]);
                    acc[i][1] = fmaf(av, b4[dk].y, acc[i][1]);
                    acc[i][2] = fmaf(av, b4[dk].z, acc[i][2]);
                    acc[i][3] = fmaf(av, b4[dk].w, acc[i][3]);
                }
            }
        }
        __syncthreads();
    }

    bool sg = (mat == sigmoidMat);
    #pragma unroll
    for (int i = 0; i < TM; i++) {
        float4 o;
        o.x = acc[i][0]; o.y = acc[i][1]; o.z = acc[i][2]; o.w = acc[i][3];
        if (sg) {
            o.x = 1.f / (1.f + expf(-o.x));
            o.y = 1.f / (1.f + expf(-o.y));
            o.z = 1.f / (1.f + expf(-o.z));
            o.w = 1.f / (1.f + expf(-o.w));
        }
        *(float4*)(Csel + (size_t)(m0 + ty * TM + i) * 128 + sub * 64 + tx * 4) = o;
    }
}

// ---------------------------------------------------------------------------
// Attention: one block (128 threads) per query row l.
//   warp w = head h; lane = key-within-tile (pass1) / output dim (pass2)
//   Pair bias computed on the fly from gathered P_LL rows (avoids the full
//   [L,L,H] bias tensor of the reference).
// ---------------------------------------------------------------------------
__global__ void __launch_bounds__(128) attn_kernel(const float* __restrict__ P,
                                                   const int* __restrict__ indices,
                                                   const float* __restrict__ Wb,
                                                   float* __restrict__ out_ao) {
    __shared__ float q_s[128];
    __shared__ float sc[H][KNN];
    __shared__ float Ks[32][129];   // reused for K then V tiles
    __shared__ float Ps[32][17];
    __shared__ int   idx_s[KNN];
    __shared__ float Wb_s[H][CP];

    int l = blockIdx.x;
    int tid = threadIdx.x;
    int lane = tid & 31;
    int w = tid >> 5;
    int h = w;

    q_s[tid]   = g_q[(size_t)l * C + tid];
    idx_s[tid] = indices[(size_t)l * KNN + tid];
    if (tid < H * CP) ((float*)Wb_s)[tid] = Wb[tid];
    __syncthreads();

    const float scale = 0.17677669529663687f;  // 1/sqrt(32)

    // ---- pass 1: scores ----
    for (int jt = 0; jt < 4; jt++) {
        #pragma unroll
        for (int rr = 0; rr < 8; rr++) {
            int r = w * 8 + rr;
            int gi = idx_s[jt * 32 + r];
            float4 kv = ((const float4*)(g_k + (size_t)gi * C))[lane];
            Ks[r][lane * 4 + 0] = kv.x;
            Ks[r][lane * 4 + 1] = kv.y;
            Ks[r][lane * 4 + 2] = kv.z;
            Ks[r][lane * 4 + 3] = kv.w;
        }
        {
            int jr = tid >> 2, part = tid & 3;
            int gi = idx_s[jt * 32 + jr];
            float4 pv = *(const float4*)(P + ((size_t)l * L + gi) * CP + part * 4);
            Ps[jr][part * 4 + 0] = pv.x;
            Ps[jr][part * 4 + 1] = pv.y;
            Ps[jr][part * 4 + 2] = pv.z;
            Ps[jr][part * 4 + 3] = pv.w;
        }
        __syncthreads();
        {
            int jj = lane;
            float s = 0.f;
            #pragma unroll
            for (int e = 0; e < DH; e++)
                s = fmaf(q_s[h * DH + e], Ks[jj][h * DH + e], s);
            s *= scale;
            float b = 0.f;
            #pragma unroll
            for (int p = 0; p < CP; p++)
                b = fmaf(Ps[jj][p], Wb_s[h][p], b);
            sc[h][jt * 32 + jj] = s + b;
        }
        __syncthreads();
    }

    // ---- softmax (warp h over 128 scores) ----
    {
        float v0 = sc[h][lane], v1 = sc[h][lane + 32];
        float v2 = sc[h][lane + 64], v3 = sc[h][lane + 96];
        float m = fmaxf(fmaxf(v0, v1), fmaxf(v2, v3));
        #pragma unroll
        for (int o = 16; o; o >>= 1) m = fmaxf(m, __shfl_xor_sync(0xffffffffu, m, o));
        v0 = expf(v0 - m); v1 = expf(v1 - m);
        v2 = expf(v2 - m); v3 = expf(v3 - m);
        float s = v0 + v1 + v2 + v3;
        #pragma unroll
        for (int o = 16; o; o >>= 1) s += __shfl_xor_sync(0xffffffffu, s, o);
        float inv = 1.f / s;
        sc[h][lane]      = v0 * inv;
        sc[h][lane + 32] = v1 * inv;
        sc[h][lane + 64] = v2 * inv;
        sc[h][lane + 96] = v3 * inv;
    }
    __syncthreads();

    // ---- pass 2: attn @ V ----
    float acc = 0.f;
    int e = lane;
    for (int jt = 0; jt < 4; jt++) {
        #pragma unroll
        for (int rr = 0; rr < 8; rr++) {
            int r = w * 8 + rr;
            int gi = idx_s[jt * 32 + r];
            float4 vv = ((const float4*)(g_v + (size_t)gi * C))[lane];
            Ks[r][lane * 4 + 0] = vv.x;
            Ks[r][lane * 4 + 1] = vv.y;
            Ks[r][lane * 4 + 2] = vv.z;
            Ks[r][lane * 4 + 3] = vv.w;
        }
        __syncthreads();
        #pragma unroll
        for (int jj = 0; jj < 32; jj++)
            acc = fmaf(sc[h][jt * 32 + jj], Ks[jj][h * DH + e], acc);
        __syncthreads();
    }

    // gate + store (c = h*32+e = tid)
    acc *= g_g[(size_t)l * C + tid];
    out_ao[(size_t)l * C + tid] = acc;
}

// ---------------------------------------------------------------------------
extern "C" void kernel_launch(void* const* d_in, const int* in_sizes, int n_in,
                              void* d_out, int out_size) {
    const float* Q_L     = (const float*)d_in[0];
    const float* P_LL    = (const float*)d_in[1];
    const int*   indices = (const int*)d_in[2];
    const float* Wq      = (const float*)d_in[3];
    const float* Wk      = (const float*)d_in[4];
    const float* Wv      = (const float*)d_in[5];
    const float* Wg      = (const float*)d_in[6];
    const float* Wb      = (const float*)d_in[7];
    const float* Wo      = (const float*)d_in[8];
    const float* ln1_w   = (const float*)d_in[9];
    const float* lnq_w   = (const float*)d_in[10];
    const float* lnk_w   = (const float*)d_in[11];
    float* out = (float*)d_out;

    float *a, *q, *k, *v, *g, *ao;
    cudaGetSymbolAddress((void**)&a,  g_a);
    cudaGetSymbolAddress((void**)&q,  g_q);
    cudaGetSymbolAddress((void**)&k,  g_k);
    cudaGetSymbolAddress((void**)&v,  g_v);
    cudaGetSymbolAddress((void**)&g,  g_g);
    cudaGetSymbolAddress((void**)&ao, g_ao);

    // 1) a = RMSNorm(Q_L, ln1_w)
    rms_kernel<<<L, 128>>>(Q_L, ln1_w, a);

    // 2) fused q/k/v/g projections (sigmoid on g)
    gemm_nt_kernel<128><<<dim3(L / 128, 8), 256>>>(
        a, Wq, Wk, Wv, Wg, q, k, v, g, /*tilesPerMat=*/2, /*sigmoidMat=*/3);

    // 3) q/k RMSNorm (in-place)
    rms_kernel<<<L, 128>>>(q, lnq_w, q);
    rms_kernel<<<L, 128>>>(k, lnk_w, k);

    // 4) attention with gathered pair bias + gate
    attn_kernel<<<L, 128>>>(P_LL, indices, Wb, ao);

    // 5) output projection
    gemm_nt_kernel<64><<<dim3(L / 64, 2), 256>>>(
        ao, Wo, Wo, Wo, Wo, out, out, out, out, /*tilesPerMat=*/2, /*sigmoidMat=*/-1);
}

// round 4
// speedup vs baseline: 1.4931x; 1.4931x over previous
#include <cuda_runtime.h>
#include <cuda_fp16.h>
#include <cstdint>

// Problem constants (D=1, L=4096, c=128, H=4, dh=32, k=128, c_pair=16)
constexpr int L   = 4096;
constexpr int C   = 128;
constexpr int H   = 4;
constexpr int KNN = 128;
constexpr int CP  = 16;

// Scratch (device globals — no allocation allowed)
__device__ float g_a [L * C];
__device__ float g_q [L * C];
__device__ float g_k [L * C];
__device__ float g_v [L * C];
__device__ float g_g [L * C];
__device__ float g_ao[L * C];
__device__ __half g_kh[L * C];
__device__ __half g_vh[L * C];

// ---------------------------------------------------------------------------
// RMSNorm: 8 rows per block, one warp per row, float4 per lane
// ---------------------------------------------------------------------------
__global__ void __launch_bounds__(256) rms8_kernel(const float* __restrict__ x,
                                                   const float* __restrict__ w,
                                                   float* __restrict__ y) {
    int row  = blockIdx.x * 8 + (threadIdx.x >> 5);
    int lane = threadIdx.x & 31;
    size_t base = (size_t)row * C + lane * 4;
    float4 v = *(const float4*)(x + base);
    float s = v.x * v.x + v.y * v.y + v.z * v.z + v.w * v.w;
    #pragma unroll
    for (int o = 16; o; o >>= 1) s += __shfl_xor_sync(0xffffffffu, s, o);
    float r = rsqrtf(s * (1.0f / C) + 1e-5f);
    float4 wv = *(const float4*)(w + lane * 4);
    v.x *= r * wv.x; v.y *= r * wv.y; v.z *= r * wv.z; v.w *= r * wv.w;
    *(float4*)(y + base) = v;
}

// ---------------------------------------------------------------------------
// Postproc: q <- rms(q)*lnq (fp32, in place), kh <- fp16(rms(k)*lnk),
//           vh <- fp16(v). One warp per row.
// ---------------------------------------------------------------------------
__global__ void __launch_bounds__(256) postproc_kernel(const float* __restrict__ lnq,
                                                       const float* __restrict__ lnk) {
    int row  = blockIdx.x * 8 + (threadIdx.x >> 5);
    int lane = threadIdx.x & 31;
    size_t base = (size_t)row * C + lane * 4;

    // q rms
    {
        float4 v = *(const float4*)(g_q + base);
        float s = v.x * v.x + v.y * v.y + v.z * v.z + v.w * v.w;
        #pragma unroll
        for (int o = 16; o; o >>= 1) s += __shfl_xor_sync(0xffffffffu, s, o);
        float r = rsqrtf(s * (1.0f / C) + 1e-5f);
        float4 wv = *(const float4*)(lnq + lane * 4);
        v.x *= r * wv.x; v.y *= r * wv.y; v.z *= r * wv.z; v.w *= r * wv.w;
        *(float4*)(g_q + base) = v;
    }
    // k rms -> fp16
    {
        float4 v = *(const float4*)(g_k + base);
        float s = v.x * v.x + v.y * v.y + v.z * v.z + v.w * v.w;
        #pragma unroll
        for (int o = 16; o; o >>= 1) s += __shfl_xor_sync(0xffffffffu, s, o);
        float r = rsqrtf(s * (1.0f / C) + 1e-5f);
        float4 wv = *(const float4*)(lnk + lane * 4);
        __half2 h0 = __floats2half2_rn(v.x * r * wv.x, v.y * r * wv.y);
        __half2 h1 = __floats2half2_rn(v.z * r * wv.z, v.w * r * wv.w);
        uint2 pk;
        pk.x = *(uint32_t*)&h0; pk.y = *(uint32_t*)&h1;
        *(uint2*)(g_kh + base) = pk;
    }
    // v -> fp16
    {
        float4 v = *(const float4*)(g_v + base);
        __half2 h0 = __floats2half2_rn(v.x, v.y);
        __half2 h1 = __floats2half2_rn(v.z, v.w);
        uint2 pk;
        pk.x = *(uint32_t*)&h0; pk.y = *(uint32_t*)&h1;
        *(uint2*)(g_vh + base) = pk;
    }
}

// ---------------------------------------------------------------------------
// GEMM  C[m][n] = sum_k A[m][k] * W[n][k], K = 128, N = 128 (full matrix),
// 8-wide-N x TM-wide-M microtile, 256 threads (16x16). blockIdx.y = matrix.
// ---------------------------------------------------------------------------
template <int BM>
__global__ void __launch_bounds__(256) gemm_kernel(
    const float* __restrict__ A,
    const float* __restrict__ W0, const float* __restrict__ W1,
    const float* __restrict__ W2, const float* __restrict__ W3,
    float* __restrict__ C0, float* __restrict__ C1,
    float* __restrict__ C2, float* __restrict__ C3,
    int sigmoidMat) {
    constexpr int TM = BM / 16;

    __shared__ float Asm[32][BM + 4];   // [k][m] transposed
    __shared__ float Bsm[32][132];      // [k][n] transposed

    int mat = blockIdx.y;
    const float* W = (mat == 0) ? W0 : (mat == 1) ? W1 : (mat == 2) ? W2 : W3;
    float* Cout    = (mat == 0) ? C0 : (mat == 1) ? C1 : (mat == 2) ? C2 : C3;

    int m0 = blockIdx.x * BM;
    int tx = threadIdx.x & 15;
    int ty = threadIdx.x >> 4;

    float acc[TM][8];
    #pragma unroll
    for (int i = 0; i < TM; i++)
        #pragma unroll
        for (int j = 0; j < 8; j++) acc[i][j] = 0.f;

    for (int kc = 0; kc < 4; kc++) {
        // stage A chunk transposed: Asm[k][m]
        for (int t = threadIdx.x; t < BM * 8; t += 256) {
            int m = t >> 3, k4 = t & 7;
            float4 av = *(const float4*)(A + (size_t)(m0 + m) * 128 + kc * 32 + k4 * 4);
            Asm[k4 * 4 + 0][m] = av.x;
            Asm[k4 * 4 + 1][m] = av.y;
            Asm[k4 * 4 + 2][m] = av.z;
            Asm[k4 * 4 + 3][m] = av.w;
        }
        // stage W chunk transposed: Bsm[k][n]
        for (int t = threadIdx.x; t < 1024; t += 256) {
            int n = t >> 3, k4 = t & 7;
            float4 wv = *(const float4*)(W + (size_t)n * 128 + kc * 32 + k4 * 4);
            Bsm[k4 * 4 + 0][n] = wv.x;
            Bsm[k4 * 4 + 1][n] = wv.y;
            Bsm[k4 * 4 + 2][n] = wv.z;
            Bsm[k4 * 4 + 3][n] = wv.w;
        }
        __syncthreads();

        #pragma unroll
        for (int k = 0; k < 32; k++) {
            float b[8];
            float4 b0 = *(const float4*)&Bsm[k][tx * 8];
            float4 b1 = *(const float4*)&Bsm[k][tx * 8 + 4];
            b[0] = b0.x; b[1] = b0.y; b[2] = b0.z; b[3] = b0.w;
            b[4] = b1.x; b[5] = b1.y; b[6] = b1.z; b[7] = b1.w;
            float a[TM];
            if constexpr (TM == 8) {
                float4 a0 = *(const float4*)&Asm[k][ty * 8];
                float4 a1 = *(const float4*)&Asm[k][ty * 8 + 4];
                a[0] = a0.x; a[1] = a0.y; a[2] = a0.z; a[3] = a0.w;
                a[4] = a1.x; a[5] = a1.y; a[6] = a1.z; a[7] = a1.w;
            } else {
                float2 a0 = *(const float2*)&Asm[k][ty * TM];
                a[0] = a0.x; a[1] = a0.y;
            }
            #pragma unroll
            for (int i = 0; i < TM; i++)
                #pragma unroll
                for (int j = 0; j < 8; j++)
                    acc[i][j] = fmaf(a[i], b[j], acc[i][j]);
        }
        __syncthreads();
    }

    bool sg = (mat == sigmoidMat);
    #pragma unroll
    for (int i = 0; i < TM; i++) {
        #pragma unroll
        for (int j4 = 0; j4 < 2; j4++) {
            float4 o;
            o.x = acc[i][j4 * 4 + 0];
            o.y = acc[i][j4 * 4 + 1];
            o.z = acc[i][j4 * 4 + 2];
            o.w = acc[i][j4 * 4 + 3];
            if (sg) {
                o.x = 1.f / (1.f + expf(-o.x));
                o.y = 1.f / (1.f + expf(-o.y));
                o.z = 1.f / (1.f + expf(-o.z));
                o.w = 1.f / (1.f + expf(-o.w));
            }
            *(float4*)(Cout + (size_t)(m0 + ty * TM + i) * 128 + tx * 8 + j4 * 4) = o;
        }
    }
}

// ---------------------------------------------------------------------------
// Attention: one block (128 threads) per query row l.
// Register-resident gather: each lane owns an 8-dim slice (dslot = lane&15),
// loads K/V rows as fp16 uint4 direct from L2, scores via quad shuffles,
// output via per-warp register accumulators + smem cross-warp reduce.
// ---------------------------------------------------------------------------
__global__ void __launch_bounds__(128) attn_kernel(const float* __restrict__ P,
                                                   const int* __restrict__ indices,
                                                   const float* __restrict__ Wb,
                                                   float* __restrict__ out_ao) {
    __shared__ float q_s[128];
    __shared__ float sc[H][KNN];
    __shared__ float Ps[KNN][17];
    __shared__ int   idx_s[KNN];
    __shared__ float Wb_s[H * CP];
    __shared__ float part[4][128];

    int l = blockIdx.x;
    int tid = threadIdx.x;
    int lane = tid & 31;
    int w = tid >> 5;

    q_s[tid]   = g_q[(size_t)l * C + tid];
    idx_s[tid] = indices[(size_t)l * KNN + tid];
    if (tid < H * CP) Wb_s[tid] = Wb[tid];
    __syncthreads();

    int dslot = lane & 15;       // which 8-dim slice this lane owns
    int hl = dslot >> 2;         // head containing this lane's dims

    float qreg[8];
    #pragma unroll
    for (int j = 0; j < 8; j++) qreg[j] = q_s[dslot * 8 + j];

    // stage all P rows: 128 rows x 16 floats = 512 float4
    for (int t = tid; t < 512; t += 128) {
        int j = t >> 2, p4 = t & 3;
        int gi = idx_s[j];
        float4 pv = *(const float4*)(P + ((size_t)l * L + gi) * CP + p4 * 4);
        Ps[j][p4 * 4 + 0] = pv.x;
        Ps[j][p4 * 4 + 1] = pv.y;
        Ps[j][p4 * 4 + 2] = pv.z;
        Ps[j][p4 * 4 + 3] = pv.w;
    }

    const float scale = 0.17677669529663687f;  // 1/sqrt(32)

    // ---- scores: warp w covers keys w*8..w*8+7 of each 32-key tile ----
    #pragma unroll
    for (int jt = 0; jt < 4; jt++) {
        #pragma unroll
        for (int i = 0; i < 4; i++) {
            int kk = jt * 32 + w * 8 + i * 2 + (lane >> 4);
            int gi = idx_s[kk];
            uint4 kv = *(const uint4*)(g_kh + (size_t)gi * C + dslot * 8);
            const __half2* kp = (const __half2*)&kv;
            float s = 0.f;
            #pragma unroll
            for (int q2 = 0; q2 < 4; q2++) {
                float2 f = __half22float2(kp[q2]);
                s = fmaf(qreg[q2 * 2],     f.x, s);
                s = fmaf(qreg[q2 * 2 + 1], f.y, s);
            }
            s += __shfl_xor_sync(0xffffffffu, s, 1);
            s += __shfl_xor_sync(0xffffffffu, s, 2);
            if ((lane & 3) == 0) sc[hl][kk] = s * scale;
        }
    }
    __syncthreads();

    // ---- add pair bias: thread (h = tid>>5, j0 = tid&31) ----
    {
        int h = tid >> 5, j0 = tid & 31;
        #pragma unroll
        for (int jt = 0; jt < 4; jt++) {
            int j = jt * 32 + j0;
            float b = 0.f;
            #pragma unroll
            for (int p = 0; p < CP; p++)
                b = fmaf(Ps[j][p], Wb_s[h * CP + p], b);
            sc[h][j] += b;
        }
    }
    __syncthreads();

    // ---- softmax: warp w handles head w over 128 scores ----
    {
        float v0 = sc[w][lane],      v1 = sc[w][lane + 32];
        float v2 = sc[w][lane + 64], v3 = sc[w][lane + 96];
        float m = fmaxf(fmaxf(v0, v1), fmaxf(v2, v3));
        #pragma unroll
        for (int o = 16; o; o >>= 1) m = fmaxf(m, __shfl_xor_sync(0xffffffffu, m, o));
        v0 = __expf(v0 - m); v1 = __expf(v1 - m);
        v2 = __expf(v2 - m); v3 = __expf(v3 - m);
        float s = v0 + v1 + v2 + v3;
        #pragma unroll
        for (int o = 16; o; o >>= 1) s += __shfl_xor_sync(0xffffffffu, s, o);
        float inv = 1.f / s;
        sc[w][lane]      = v0 * inv;
        sc[w][lane + 32] = v1 * inv;
        sc[w][lane + 64] = v2 * inv;
        sc[w][lane + 96] = v3 * inv;
    }
    __syncthreads();

    // ---- attn @ V: register accumulation over this warp's keys ----
    float acc[8];
    #pragma unroll
    for (int j = 0; j < 8; j++) acc[j] = 0.f;

    #pragma unroll
    for (int jt = 0; jt < 4; jt++) {
        #pragma unroll
        for (int i = 0; i < 4; i++) {
            int kk = jt * 32 + w * 8 + i * 2 + (lane >> 4);
            int gi = idx_s[kk];
            uint4 vv = *(const uint4*)(g_vh + (size_t)gi * C + dslot * 8);
            const __half2* vp = (const __half2*)&vv;
            float p = sc[hl][kk];
            #pragma unroll
            for (int q2 = 0; q2 < 4; q2++) {
                float2 f = __half22float2(vp[q2]);
                acc[q2 * 2]     = fmaf(p, f.x, acc[q2 * 2]);
                acc[q2 * 2 + 1] = fmaf(p, f.y, acc[q2 * 2 + 1]);
            }
        }
    }
    // merge the two half-warps (same dims, different keys)
    #pragma unroll
    for (int j = 0; j < 8; j++) acc[j] += __shfl_xor_sync(0xffffffffu, acc[j], 16);
    if (lane < 16) {
        #pragma unroll
        for (int j = 0; j < 8; j++) part[w][dslot * 8 + j] = acc[j];
    }
    __syncthreads();

    float o = part[0][tid] + part[1][tid] + part[2][tid] + part[3][tid];
    o *= g_g[(size_t)l * C + tid];
    out_ao[(size_t)l * C + tid] = o;
}

// ---------------------------------------------------------------------------
extern "C" void kernel_launch(void* const* d_in, const int* in_sizes, int n_in,
                              void* d_out, int out_size) {
    const float* Q_L     = (const float*)d_in[0];
    const float* P_LL    = (const float*)d_in[1];
    const int*   indices = (const int*)d_in[2];
    const float* Wq      = (const float*)d_in[3];
    const float* Wk      = (const float*)d_in[4];
    const float* Wv      = (const float*)d_in[5];
    const float* Wg      = (const float*)d_in[6];
    const float* Wb      = (const float*)d_in[7];
    const float* Wo      = (const float*)d_in[8];
    const float* ln1_w   = (const float*)d_in[9];
    const float* lnq_w   = (const float*)d_in[10];
    const float* lnk_w   = (const float*)d_in[11];
    float* out = (float*)d_out;

    float *a, *q, *k, *v, *g, *ao;
    cudaGetSymbolAddress((void**)&a,  g_a);
    cudaGetSymbolAddress((void**)&q,  g_q);
    cudaGetSymbolAddress((void**)&k,  g_k);
    cudaGetSymbolAddress((void**)&v,  g_v);
    cudaGetSymbolAddress((void**)&g,  g_g);
    cudaGetSymbolAddress((void**)&ao, g_ao);

    // 1) a = RMSNorm(Q_L, ln1_w)
    rms8_kernel<<<L / 8, 256>>>(Q_L, ln1_w, a);

    // 2) fused q/k/v/g projections (sigmoid on g)
    gemm_kernel<128><<<dim3(L / 128, 4), 256>>>(
        a, Wq, Wk, Wv, Wg, q, k, v, g, /*sigmoidMat=*/3);

    // 3) q-rms (fp32), k-rms -> fp16, v -> fp16
    postproc_kernel<<<L / 8, 256>>>(lnq_w, lnk_w);

    // 4) attention with gathered pair bias + gate
    attn_kernel<<<L, 128>>>(P_LL, indices, Wb, ao);

    // 5) output projection
    gemm_kernel<32><<<dim3(L / 32, 1), 256>>>(
        ao, Wo, Wo, Wo, Wo, out, out, out, out, /*sigmoidMat=*/-1);
}

// round 5
// speedup vs baseline: 2.2397x; 1.5000x over previous
#include <cuda_runtime.h>
#include <cuda_fp16.h>
#include <cstdint>

// Problem constants (D=1, L=4096, c=128, H=4, dh=32, k=128, c_pair=16)
constexpr int L   = 4096;
constexpr int C   = 128;
constexpr int H   = 4;
constexpr int KNN = 128;
constexpr int CP  = 16;

// Scratch (device globals — no allocation allowed)
__device__ float g_a [L * C];
__device__ float g_q [L * C];
__device__ float g_k [L * C];
__device__ float g_v [L * C];
__device__ float g_g [L * C];
__device__ float g_ao[L * C];
__device__ __half g_kh[L * C];
__device__ __half g_vh[L * C];

// ---------------------------------------------------------------------------
// RMSNorm: 8 rows per block, one warp per row, float4 per lane
// ---------------------------------------------------------------------------
__global__ void __launch_bounds__(256) rms8_kernel(const float* __restrict__ x,
                                                   const float* __restrict__ w,
                                                   float* __restrict__ y) {
    int row  = blockIdx.x * 8 + (threadIdx.x >> 5);
    int lane = threadIdx.x & 31;
    size_t base = (size_t)row * C + lane * 4;
    float4 v = *(const float4*)(x + base);
    float s = v.x * v.x + v.y * v.y + v.z * v.z + v.w * v.w;
    #pragma unroll
    for (int o = 16; o; o >>= 1) s += __shfl_xor_sync(0xffffffffu, s, o);
    float r = rsqrtf(s * (1.0f / C) + 1e-5f);
    float4 wv = *(const float4*)(w + lane * 4);
    v.x *= r * wv.x; v.y *= r * wv.y; v.z *= r * wv.z; v.w *= r * wv.w;
    *(float4*)(y + base) = v;
}

// ---------------------------------------------------------------------------
// Postproc: q <- rms(q)*lnq (fp32, in place), kh <- fp16(rms(k)*lnk),
//           vh <- fp16(v). One warp per row.
// ---------------------------------------------------------------------------
__global__ void __launch_bounds__(256) postproc_kernel(const float* __restrict__ lnq,
                                                       const float* __restrict__ lnk) {
    int row  = blockIdx.x * 8 + (threadIdx.x >> 5);
    int lane = threadIdx.x & 31;
    size_t base = (size_t)row * C + lane * 4;

    {
        float4 v = *(const float4*)(g_q + base);
        float s = v.x * v.x + v.y * v.y + v.z * v.z + v.w * v.w;
        #pragma unroll
        for (int o = 16; o; o >>= 1) s += __shfl_xor_sync(0xffffffffu, s, o);
        float r = rsqrtf(s * (1.0f / C) + 1e-5f);
        float4 wv = *(const float4*)(lnq + lane * 4);
        v.x *= r * wv.x; v.y *= r * wv.y; v.z *= r * wv.z; v.w *= r * wv.w;
        *(float4*)(g_q + base) = v;
    }
    {
        float4 v = *(const float4*)(g_k + base);
        float s = v.x * v.x + v.y * v.y + v.z * v.z + v.w * v.w;
        #pragma unroll
        for (int o = 16; o; o >>= 1) s += __shfl_xor_sync(0xffffffffu, s, o);
        float r = rsqrtf(s * (1.0f / C) + 1e-5f);
        float4 wv = *(const float4*)(lnk + lane * 4);
        __half2 h0 = __floats2half2_rn(v.x * r * wv.x, v.y * r * wv.y);
        __half2 h1 = __floats2half2_rn(v.z * r * wv.z, v.w * r * wv.w);
        uint2 pk;
        pk.x = *(uint32_t*)&h0; pk.y = *(uint32_t*)&h1;
        *(uint2*)(g_kh + base) = pk;
    }
    {
        float4 v = *(const float4*)(g_v + base);
        __half2 h0 = __floats2half2_rn(v.x, v.y);
        __half2 h1 = __floats2half2_rn(v.z, v.w);
        uint2 pk;
        pk.x = *(uint32_t*)&h0; pk.y = *(uint32_t*)&h1;
        *(uint2*)(g_vh + base) = pk;
    }
}

// ---------------------------------------------------------------------------
// tf32 helpers
// ---------------------------------------------------------------------------
__device__ __forceinline__ float to_tf32(float x) {
    uint32_t u;
    asm("cvt.rna.tf32.f32 %0, %1;" : "=r"(u) : "f"(x));
    return __uint_as_float(u);
}

__device__ __forceinline__ void mma_tf32(float* c, const uint32_t* a, const uint32_t* b) {
    asm("mma.sync.aligned.m16n8k8.row.col.f32.tf32.tf32.f32 "
        "{%0,%1,%2,%3},{%4,%5,%6,%7},{%8,%9},{%0,%1,%2,%3};"
        : "+f"(c[0]), "+f"(c[1]), "+f"(c[2]), "+f"(c[3])
        : "r"(a[0]), "r"(a[1]), "r"(a[2]), "r"(a[3]), "r"(b[0]), "r"(b[1]));
}

// ---------------------------------------------------------------------------
// tf32 tensor-core GEMM: C[m][n] = sum_k A[m][k] * W[n][k]; K = 128 fixed.
// 8 warps = WM x WN; warp tile = (TM*16) x (TN*8); BN fixed at 64.
// blockIdx.y = mat*2 + nhalf. Optional sigmoid epilogue.
// ---------------------------------------------------------------------------
template <int WM, int WN, int TM, int TN>
__global__ void __launch_bounds__(256) gemm_tf32_kernel(
    const float* __restrict__ A,
    const float* __restrict__ W0, const float* __restrict__ W1,
    const float* __restrict__ W2, const float* __restrict__ W3,
    float* __restrict__ C0, float* __restrict__ C1,
    float* __restrict__ C2, float* __restrict__ C3,
    int sigmoidMat) {
    constexpr int BM = WM * TM * 16;
    static_assert(WN * TN * 8 == 64, "BN must be 64");
    static_assert(WM * WN == 8, "8 warps");

    __shared__ float As[BM][36];    // [m][k-chunk 0..31], stride 36 floats (144B, 16B-aligned)
    __shared__ float Bs[64][132];   // [n][k 0..127],      stride 132 floats (528B, 16B-aligned)

    int mat   = blockIdx.y >> 1;
    int nhalf = blockIdx.y & 1;
    const float* W = (mat == 0) ? W0 : (mat == 1) ? W1 : (mat == 2) ? W2 : W3;
    float* Cout    = (mat == 0) ? C0 : (mat == 1) ? C1 : (mat == 2) ? C2 : C3;

    int m0 = blockIdx.x * BM;
    int n0 = nhalf * 64;
    int tid = threadIdx.x;
    int lane = tid & 31;
    int wid  = tid >> 5;
    int warp_m = wid % WM;
    int warp_n = wid / WM;
    int lr = lane >> 2;   // 0..7
    int lc = lane & 3;    // 0..3

    // stage B (whole 64 x 128), converted to tf32
    for (int t = tid; t < 64 * 32; t += 256) {
        int n = t >> 5, k4 = t & 31;
        float4 w = *(const float4*)(W + (size_t)(n0 + n) * 128 + k4 * 4);
        float4 c;
        c.x = to_tf32(w.x); c.y = to_tf32(w.y);
        c.z = to_tf32(w.z); c.w = to_tf32(w.w);
        *(float4*)&Bs[n][k4 * 4] = c;
    }

    float acc[TM][TN][4];
    #pragma unroll
    for (int i = 0; i < TM; i++)
        #pragma unroll
        for (int j = 0; j < TN; j++)
            #pragma unroll
            for (int r = 0; r < 4; r++) acc[i][j][r] = 0.f;

    for (int kc = 0; kc < 4; kc++) {
        for (int t = tid; t < BM * 8; t += 256) {
            int m = t >> 3, k4 = t & 7;
            float4 av = *(const float4*)(A + (size_t)(m0 + m) * 128 + kc * 32 + k4 * 4);
            float4 c;
            c.x = to_tf32(av.x); c.y = to_tf32(av.y);
            c.z = to_tf32(av.z); c.w = to_tf32(av.w);
            *(float4*)&As[m][k4 * 4] = c;
        }
        __syncthreads();

        #pragma unroll
        for (int ks = 0; ks < 4; ks++) {
            int kk = ks * 8 + lc;           // local k in chunk
            int kB = kc * 32 + kk;          // global k for Bs
            uint32_t a[TM][4], b[TN][2];
            #pragma unroll
            for (int tm = 0; tm < TM; tm++) {
                int r = warp_m * (TM * 16) + tm * 16 + lr;
                a[tm][0] = __float_as_uint(As[r][kk]);
                a[tm][1] = __float_as_uint(As[r + 8][kk]);
                a[tm][2] = __float_as_uint(As[r][kk + 4]);
                a[tm][3] = __float_as_uint(As[r + 8][kk + 4]);
            }
            #pragma unroll
            for (int tn = 0; tn < TN; tn++) {
                int cidx = warp_n * (TN * 8) + tn * 8 + lr;
                b[tn][0] = __float_as_uint(Bs[cidx][kB]);
                b[tn][1] = __float_as_uint(Bs[cidx][kB + 4]);
            }
            #pragma unroll
            for (int tm = 0; tm < TM; tm++)
                #pragma unroll
                for (int tn = 0; tn < TN; tn++)
                    mma_tf32(acc[tm][tn], a[tm], b[tn]);
        }
        __syncthreads();
    }

    bool sg = (mat == sigmoidMat);
    #pragma unroll
    for (int tm = 0; tm < TM; tm++) {
        #pragma unroll
        for (int tn = 0; tn < TN; tn++) {
            int r = m0 + warp_m * (TM * 16) + tm * 16 + lr;
            int cc = n0 + warp_n * (TN * 8) + tn * 8 + 2 * lc;
            float2 v0, v1;
            v0.x = acc[tm][tn][0]; v0.y = acc[tm][tn][1];
            v1.x = acc[tm][tn][2]; v1.y = acc[tm][tn][3];
            if (sg) {
                v0.x = 1.f / (1.f + expf(-v0.x));
                v0.y = 1.f / (1.f + expf(-v0.y));
                v1.x = 1.f / (1.f + expf(-v1.x));
                v1.y = 1.f / (1.f + expf(-v1.y));
            }
            *(float2*)(Cout + (size_t)r * 128 + cc)       = v0;
            *(float2*)(Cout + (size_t)(r + 8) * 128 + cc) = v1;
        }
    }
}

// ---------------------------------------------------------------------------
// Attention: one block (128 threads) per query row l.
// P rows prefetched into registers before the K score phase (latency overlap);
// bias added in-place afterward. sc rows padded to kill head bank conflicts.
// ---------------------------------------------------------------------------
__global__ void __launch_bounds__(128) attn_kernel(const float* __restrict__ P,
                                                   const int* __restrict__ indices,
                                                   const float* __restrict__ Wb,
                                                   float* __restrict__ out_ao) {
    __shared__ float q_s[128];
    __shared__ float sc[H][132];
    __shared__ int   idx_s[KNN];
    __shared__ float Wb_s[H * CP];
    __shared__ float part[4][128];

    int l = blockIdx.x;
    int tid = threadIdx.x;
    int lane = tid & 31;
    int w = tid >> 5;

    q_s[tid]   = g_q[(size_t)l * C + tid];
    idx_s[tid] = indices[(size_t)l * KNN + tid];
    if (tid < H * CP) Wb_s[tid] = Wb[tid];
    __syncthreads();

    int dslot = lane & 15;       // which 8-dim slice this lane owns
    int hl = dslot >> 2;         // head containing this lane's dims

    // prefetch this thread's P row (row j = tid) into registers (DRAM latency
    // overlaps with the score phase below)
    float pr[16];
    {
        const float4* pp = (const float4*)(P + ((size_t)l * L + idx_s[tid]) * CP);
        float4 p0 = pp[0], p1 = pp[1], p2 = pp[2], p3 = pp[3];
        pr[0]=p0.x; pr[1]=p0.y; pr[2]=p0.z; pr[3]=p0.w;
        pr[4]=p1.x; pr[5]=p1.y; pr[6]=p1.z; pr[7]=p1.w;
        pr[8]=p2.x; pr[9]=p2.y; pr[10]=p2.z; pr[11]=p2.w;
        pr[12]=p3.x; pr[13]=p3.y; pr[14]=p3.z; pr[15]=p3.w;
    }

    float qreg[8];
    #pragma unroll
    for (int j = 0; j < 8; j++) qreg[j] = q_s[dslot * 8 + j];

    const float scale = 0.17677669529663687f;  // 1/sqrt(32)

    // ---- scores: warp w covers keys w*8..w*8+7 of each 32-key tile ----
    #pragma unroll
    for (int jt = 0; jt < 4; jt++) {
        #pragma unroll
        for (int i = 0; i < 4; i++) {
            int kk = jt * 32 + w * 8 + i * 2 + (lane >> 4);
            int gi = idx_s[kk];
            uint4 kv = *(const uint4*)(g_kh + (size_t)gi * C + dslot * 8);
            const __half2* kp = (const __half2*)&kv;
            float s = 0.f;
            #pragma unroll
            for (int q2 = 0; q2 < 4; q2++) {
                float2 f = __half22float2(kp[q2]);
                s = fmaf(qreg[q2 * 2],     f.x, s);
                s = fmaf(qreg[q2 * 2 + 1], f.y, s);
            }
            s += __shfl_xor_sync(0xffffffffu, s, 1);
            s += __shfl_xor_sync(0xffffffffu, s, 2);
            if ((lane & 3) == 0) sc[hl][kk] = s * scale;
        }
    }
    __syncthreads();

    // ---- add pair bias from registers: thread tid owns key row tid ----
    #pragma unroll
    for (int h = 0; h < H; h++) {
        float b = 0.f;
        #pragma unroll
        for (int p = 0; p < CP; p++)
            b = fmaf(pr[p], Wb_s[h * CP + p], b);
        sc[h][tid] += b;
    }
    __syncthreads();

    // ---- softmax: warp w handles head w over 128 scores ----
    {
        float v0 = sc[w][lane],      v1 = sc[w][lane + 32];
        float v2 = sc[w][lane + 64], v3 = sc[w][lane + 96];
        float m = fmaxf(fmaxf(v0, v1), fmaxf(v2, v3));
        #pragma unroll
        for (int o = 16; o; o >>= 1) m = fmaxf(m, __shfl_xor_sync(0xffffffffu, m, o));
        v0 = __expf(v0 - m); v1 = __expf(v1 - m);
        v2 = __expf(v2 - m); v3 = __expf(v3 - m);
        float s = v0 + v1 + v2 + v3;
        #pragma unroll
        for (int o = 16; o; o >>= 1) s += __shfl_xor_sync(0xffffffffu, s, o);
        float inv = 1.f / s;
        sc[w][lane]      = v0 * inv;
        sc[w][lane + 32] = v1 * inv;
        sc[w][lane + 64] = v2 * inv;
        sc[w][lane + 96] = v3 * inv;
    }
    __syncthreads();

    // ---- attn @ V: register accumulation over this warp's keys ----
    float acc[8];
    #pragma unroll
    for (int j = 0; j < 8; j++) acc[j] = 0.f;

    #pragma unroll
    for (int jt = 0; jt < 4; jt++) {
        #pragma unroll
        for (int i = 0; i < 4; i++) {
            int kk = jt * 32 + w * 8 + i * 2 + (lane >> 4);
            int gi = idx_s[kk];
            uint4 vv = *(const uint4*)(g_vh + (size_t)gi * C + dslot * 8);
            const __half2* vp = (const __half2*)&vv;
            float p = sc[hl][kk];
            #pragma unroll
            for (int q2 = 0; q2 < 4; q2++) {
                float2 f = __half22float2(vp[q2]);
                acc[q2 * 2]     = fmaf(p, f.x, acc[q2 * 2]);
                acc[q2 * 2 + 1] = fmaf(p, f.y, acc[q2 * 2 + 1]);
            }
        }
    }
    #pragma unroll
    for (int j = 0; j < 8; j++) acc[j] += __shfl_xor_sync(0xffffffffu, acc[j], 16);
    if (lane < 16) {
        #pragma unroll
        for (int j = 0; j < 8; j++) part[w][dslot * 8 + j] = acc[j];
    }
    __syncthreads();

    float o = part[0][tid] + part[1][tid] + part[2][tid] + part[3][tid];
    o *= g_g[(size_t)l * C + tid];
    out_ao[(size_t)l * C + tid] = o;
}

// ---------------------------------------------------------------------------
extern "C" void kernel_launch(void* const* d_in, const int* in_sizes, int n_in,
                              void* d_out, int out_size) {
    const float* Q_L     = (const float*)d_in[0];
    const float* P_LL    = (const float*)d_in[1];
    const int*   indices = (const int*)d_in[2];
    const float* Wq      = (const float*)d_in[3];
    const float* Wk      = (const float*)d_in[4];
    const float* Wv      = (const float*)d_in[5];
    const float* Wg      = (const float*)d_in[6];
    const float* Wb      = (const float*)d_in[7];
    const float* Wo      = (const float*)d_in[8];
    const float* ln1_w   = (const float*)d_in[9];
    const float* lnq_w   = (const float*)d_in[10];
    const float* lnk_w   = (const float*)d_in[11];
    float* out = (float*)d_out;

    float *a, *q, *k, *v, *g, *ao;
    cudaGetSymbolAddress((void**)&a,  g_a);
    cudaGetSymbolAddress((void**)&q,  g_q);
    cudaGetSymbolAddress((void**)&k,  g_k);
    cudaGetSymbolAddress((void**)&v,  g_v);
    cudaGetSymbolAddress((void**)&g,  g_g);
    cudaGetSymbolAddress((void**)&ao, g_ao);

    // 1) a = RMSNorm(Q_L, ln1_w)
    rms8_kernel<<<L / 8, 256>>>(Q_L, ln1_w, a);

    // 2) fused q/k/v/g projections, tf32 tensor cores (sigmoid on g)
    gemm_tf32_kernel<4, 2, 2, 4><<<dim3(L / 128, 8), 256>>>(
        a, Wq, Wk, Wv, Wg, q, k, v, g, /*sigmoidMat=*/3);

    // 3) q-rms (fp32), k-rms -> fp16, v -> fp16
    postproc_kernel<<<L / 8, 256>>>(lnq_w, lnk_w);

    // 4) attention with gathered pair bias + gate
    attn_kernel<<<L, 128>>>(P_LL, indices, Wb, ao);

    // 5) output projection, tf32 tensor cores
    gemm_tf32_kernel<2, 4, 2, 2><<<dim3(L / 64, 2), 256>>>(
        ao, Wo, Wo, Wo, Wo, out, out, out, out, /*sigmoidMat=*/-1);
}

// round 6
// speedup vs baseline: 2.2408x; 1.0005x over previous
#include <cuda_runtime.h>
#include <cuda_fp16.h>
#include <cstdint>

// Problem constants (D=1, L=4096, c=128, H=4, dh=32, k=128, c_pair=16)
constexpr int L   = 4096;
constexpr int C   = 128;
constexpr int H   = 4;
constexpr int KNN = 128;
constexpr int CP  = 16;

// Scratch (device globals — no allocation allowed)
__device__ float g_a [L * C];
__device__ float g_q [L * C];
__device__ float g_k [L * C];
__device__ float g_v [L * C];
__device__ float g_g [L * C];
__device__ float g_ao[L * C];
__device__ __half g_kh[L * C];
__device__ __half g_vh[L * C];

// ---------------------------------------------------------------------------
// RMSNorm: 8 rows per block, one warp per row, float4 per lane
// ---------------------------------------------------------------------------
__global__ void __launch_bounds__(256) rms8_kernel(const float* __restrict__ x,
                                                   const float* __restrict__ w,
                                                   float* __restrict__ y) {
    int row  = blockIdx.x * 8 + (threadIdx.x >> 5);
    int lane = threadIdx.x & 31;
    size_t base = (size_t)row * C + lane * 4;
    float4 v = *(const float4*)(x + base);
    float s = v.x * v.x + v.y * v.y + v.z * v.z + v.w * v.w;
    #pragma unroll
    for (int o = 16; o; o >>= 1) s += __shfl_xor_sync(0xffffffffu, s, o);
    float r = rsqrtf(s * (1.0f / C) + 1e-5f);
    float4 wv = *(const float4*)(w + lane * 4);
    v.x *= r * wv.x; v.y *= r * wv.y; v.z *= r * wv.z; v.w *= r * wv.w;
    *(float4*)(y + base) = v;
}

// ---------------------------------------------------------------------------
// Postproc: q <- rms(q)*lnq (fp32, in place), kh <- fp16(rms(k)*lnk),
//           vh <- fp16(v). One warp per row.
// ---------------------------------------------------------------------------
__global__ void __launch_bounds__(256) postproc_kernel(const float* __restrict__ lnq,
                                                       const float* __restrict__ lnk) {
    int row  = blockIdx.x * 8 + (threadIdx.x >> 5);
    int lane = threadIdx.x & 31;
    size_t base = (size_t)row * C + lane * 4;

    {
        float4 v = *(const float4*)(g_q + base);
        float s = v.x * v.x + v.y * v.y + v.z * v.z + v.w * v.w;
        #pragma unroll
        for (int o = 16; o; o >>= 1) s += __shfl_xor_sync(0xffffffffu, s, o);
        float r = rsqrtf(s * (1.0f / C) + 1e-5f);
        float4 wv = *(const float4*)(lnq + lane * 4);
        v.x *= r * wv.x; v.y *= r * wv.y; v.z *= r * wv.z; v.w *= r * wv.w;
        *(float4*)(g_q + base) = v;
    }
    {
        float4 v = *(const float4*)(g_k + base);
        float s = v.x * v.x + v.y * v.y + v.z * v.z + v.w * v.w;
        #pragma unroll
        for (int o = 16; o; o >>= 1) s += __shfl_xor_sync(0xffffffffu, s, o);
        float r = rsqrtf(s * (1.0f / C) + 1e-5f);
        float4 wv = *(const float4*)(lnk + lane * 4);
        __half2 h0 = __floats2half2_rn(v.x * r * wv.x, v.y * r * wv.y);
        __half2 h1 = __floats2half2_rn(v.z * r * wv.z, v.w * r * wv.w);
        uint2 pk;
        pk.x = *(uint32_t*)&h0; pk.y = *(uint32_t*)&h1;
        *(uint2*)(g_kh + base) = pk;
    }
    {
        float4 v = *(const float4*)(g_v + base);
        __half2 h0 = __floats2half2_rn(v.x, v.y);
        __half2 h1 = __floats2half2_rn(v.z, v.w);
        uint2 pk;
        pk.x = *(uint32_t*)&h0; pk.y = *(uint32_t*)&h1;
        *(uint2*)(g_vh + base) = pk;
    }
}

// ---------------------------------------------------------------------------
// tf32 helpers
// ---------------------------------------------------------------------------
__device__ __forceinline__ float to_tf32(float x) {
    uint32_t u;
    asm("cvt.rna.tf32.f32 %0, %1;" : "=r"(u) : "f"(x));
    return __uint_as_float(u);
}

__device__ __forceinline__ void mma_tf32(float* c, const uint32_t* a, const uint32_t* b) {
    asm("mma.sync.aligned.m16n8k8.row.col.f32.tf32.tf32.f32 "
        "{%0,%1,%2,%3},{%4,%5,%6,%7},{%8,%9},{%0,%1,%2,%3};"
        : "+f"(c[0]), "+f"(c[1]), "+f"(c[2]), "+f"(c[3])
        : "r"(a[0]), "r"(a[1]), "r"(a[2]), "r"(a[3]), "r"(b[0]), "r"(b[1]));
}

// ---------------------------------------------------------------------------
// tf32 tensor-core GEMM: C[m][n] = sum_k A[m][k] * W[n][k]; K = 128 fixed.
// 8 warps = WM x WN; warp tile = (TM*16) x (TN*8); BN fixed at 64.
// blockIdx.y = mat*2 + nhalf. Optional sigmoid epilogue.
// ---------------------------------------------------------------------------
template <int WM, int WN, int TM, int TN>
__global__ void __launch_bounds__(256) gemm_tf32_kernel(
    const float* __restrict__ A,
    const float* __restrict__ W0, const float* __restrict__ W1,
    const float* __restrict__ W2, const float* __restrict__ W3,
    float* __restrict__ C0, float* __restrict__ C1,
    float* __restrict__ C2, float* __restrict__ C3,
    int sigmoidMat) {
    constexpr int BM = WM * TM * 16;
    static_assert(WN * TN * 8 == 64, "BN must be 64");
    static_assert(WM * WN == 8, "8 warps");

    __shared__ float As[BM][36];    // [m][k-chunk 0..31], stride 36 floats (144B, 16B-aligned)
    __shared__ float Bs[64][132];   // [n][k 0..127],      stride 132 floats (528B, 16B-aligned)

    int mat   = blockIdx.y >> 1;
    int nhalf = blockIdx.y & 1;
    const float* W = (mat == 0) ? W0 : (mat == 1) ? W1 : (mat == 2) ? W2 : W3;
    float* Cout    = (mat == 0) ? C0 : (mat == 1) ? C1 : (mat == 2) ? C2 : C3;

    int m0 = blockIdx.x * BM;
    int n0 = nhalf * 64;
    int tid = threadIdx.x;
    int lane = tid & 31;
    int wid  = tid >> 5;
    int warp_m = wid % WM;
    int warp_n = wid / WM;
    int lr = lane >> 2;   // 0..7
    int lc = lane & 3;    // 0..3

    // stage B (whole 64 x 128), converted to tf32
    for (int t = tid; t < 64 * 32; t += 256) {
        int n = t >> 5, k4 = t & 31;
        float4 w = *(const float4*)(W + (size_t)(n0 + n) * 128 + k4 * 4);
        float4 c;
        c.x = to_tf32(w.x); c.y = to_tf32(w.y);
        c.z = to_tf32(w.z); c.w = to_tf32(w.w);
        *(float4*)&Bs[n][k4 * 4] = c;
    }

    float acc[TM][TN][4];
    #pragma unroll
    for (int i = 0; i < TM; i++)
        #pragma unroll
        for (int j = 0; j < TN; j++)
            #pragma unroll
            for (int r = 0; r < 4; r++) acc[i][j][r] = 0.f;

    for (int kc = 0; kc < 4; kc++) {
        for (int t = tid; t < BM * 8; t += 256) {
            int m = t >> 3, k4 = t & 7;
            float4 av = *(const float4*)(A + (size_t)(m0 + m) * 128 + kc * 32 + k4 * 4);
            float4 c;
            c.x = to_tf32(av.x); c.y = to_tf32(av.y);
            c.z = to_tf32(av.z); c.w = to_tf32(av.w);
            *(float4*)&As[m][k4 * 4] = c;
        }
        __syncthreads();

        #pragma unroll
        for (int ks = 0; ks < 4; ks++) {
            int kk = ks * 8 + lc;           // local k in chunk
            int kB = kc * 32 + kk;          // global k for Bs
            uint32_t a[TM][4], b[TN][2];
            #pragma unroll
            for (int tm = 0; tm < TM; tm++) {
                int r = warp_m * (TM * 16) + tm * 16 + lr;
                a[tm][0] = __float_as_uint(As[r][kk]);
                a[tm][1] = __float_as_uint(As[r + 8][kk]);
                a[tm][2] = __float_as_uint(As[r][kk + 4]);
                a[tm][3] = __float_as_uint(As[r + 8][kk + 4]);
            }
            #pragma unroll
            for (int tn = 0; tn < TN; tn++) {
                int cidx = warp_n * (TN * 8) + tn * 8 + lr;
                b[tn][0] = __float_as_uint(Bs[cidx][kB]);
                b[tn][1] = __float_as_uint(Bs[cidx][kB + 4]);
            }
            #pragma unroll
            for (int tm = 0; tm < TM; tm++)
                #pragma unroll
                for (int tn = 0; tn < TN; tn++)
                    mma_tf32(acc[tm][tn], a[tm], b[tn]);
        }
        __syncthreads();
    }

    bool sg = (mat == sigmoidMat);
    #pragma unroll
    for (int tm = 0; tm < TM; tm++) {
        #pragma unroll
        for (int tn = 0; tn < TN; tn++) {
            int r = m0 + warp_m * (TM * 16) + tm * 16 + lr;
            int cc = n0 + warp_n * (TN * 8) + tn * 8 + 2 * lc;
            float2 v0, v1;
            v0.x = acc[tm][tn][0]; v0.y = acc[tm][tn][1];
            v1.x = acc[tm][tn][2]; v1.y = acc[tm][tn][3];
            if (sg) {
                v0.x = 1.f / (1.f + expf(-v0.x));
                v0.y = 1.f / (1.f + expf(-v0.y));
                v1.x = 1.f / (1.f + expf(-v1.x));
                v1.y = 1.f / (1.f + expf(-v1.y));
            }
            *(float2*)(Cout + (size_t)r * 128 + cc)       = v0;
            *(float2*)(Cout + (size_t)(r + 8) * 128 + cc) = v1;
        }
    }
}

// ---------------------------------------------------------------------------
// Attention: one block (128 threads) per query row l.
// P rows prefetched into registers before the K score phase (latency overlap);
// bias added in-place afterward. sc rows padded to kill head bank conflicts.
// ---------------------------------------------------------------------------
__global__ void __launch_bounds__(128) attn_kernel(const float* __restrict__ P,
                                                   const int* __restrict__ indices,
                                                   const float* __restrict__ Wb,
                                                   float* __restrict__ out_ao) {
    __shared__ float q_s[128];
    __shared__ float sc[H][132];
    __shared__ int   idx_s[KNN];
    __shared__ float Wb_s[H * CP];
    __shared__ float part[4][128];

    int l = blockIdx.x;
    int tid = threadIdx.x;
    int lane = tid & 31;
    int w = tid >> 5;

    q_s[tid]   = g_q[(size_t)l * C + tid];
    idx_s[tid] = indices[(size_t)l * KNN + tid];
    if (tid < H * CP) Wb_s[tid] = Wb[tid];
    __syncthreads();

    int dslot = lane & 15;       // which 8-dim slice this lane owns
    int hl = dslot >> 2;         // head containing this lane's dims

    // prefetch this thread's P row (row j = tid) into registers (DRAM latency
    // overlaps with the score phase below)
    float pr[16];
    {
        const float4* pp = (const float4*)(P + ((size_t)l * L + idx_s[tid]) * CP);
        float4 p0 = pp[0], p1 = pp[1], p2 = pp[2], p3 = pp[3];
        pr[0]=p0.x; pr[1]=p0.y; pr[2]=p0.z; pr[3]=p0.w;
        pr[4]=p1.x; pr[5]=p1.y; pr[6]=p1.z; pr[7]=p1.w;
        pr[8]=p2.x; pr[9]=p2.y; pr[10]=p2.z; pr[11]=p2.w;
        pr[12]=p3.x; pr[13]=p3.y; pr[14]=p3.z; pr[15]=p3.w;
    }

    float qreg[8];
    #pragma unroll
    for (int j = 0; j < 8; j++) qreg[j] = q_s[dslot * 8 + j];

    const float scale = 0.17677669529663687f;  // 1/sqrt(32)

    // ---- scores: warp w covers keys w*8..w*8+7 of each 32-key tile ----
    #pragma unroll
    for (int jt = 0; jt < 4; jt++) {
        #pragma unroll
        for (int i = 0; i < 4; i++) {
            int kk = jt * 32 + w * 8 + i * 2 + (lane >> 4);
            int gi = idx_s[kk];
            uint4 kv = *(const uint4*)(g_kh + (size_t)gi * C + dslot * 8);
            const __half2* kp = (const __half2*)&kv;
            float s = 0.f;
            #pragma unroll
            for (int q2 = 0; q2 < 4; q2++) {
                float2 f = __half22float2(kp[q2]);
                s = fmaf(qreg[q2 * 2],     f.x, s);
                s = fmaf(qreg[q2 * 2 + 1], f.y, s);
            }
            s += __shfl_xor_sync(0xffffffffu, s, 1);
            s += __shfl_xor_sync(0xffffffffu, s, 2);
            if ((lane & 3) == 0) sc[hl][kk] = s * scale;
        }
    }
    __syncthreads();

    // ---- add pair bias from registers: thread tid owns key row tid ----
    #pragma unroll
    for (int h = 0; h < H; h++) {
        float b = 0.f;
        #pragma unroll
        for (int p = 0; p < CP; p++)
            b = fmaf(pr[p], Wb_s[h * CP + p], b);
        sc[h][tid] += b;
    }
    __syncthreads();

    // ---- softmax: warp w handles head w over 128 scores ----
    {
        float v0 = sc[w][lane],      v1 = sc[w][lane + 32];
        float v2 = sc[w][lane + 64], v3 = sc[w][lane + 96];
        float m = fmaxf(fmaxf(v0, v1), fmaxf(v2, v3));
        #pragma unroll
        for (int o = 16; o; o >>= 1) m = fmaxf(m, __shfl_xor_sync(0xffffffffu, m, o));
        v0 = __expf(v0 - m); v1 = __expf(v1 - m);
        v2 = __expf(v2 - m); v3 = __expf(v3 - m);
        float s = v0 + v1 + v2 + v3;
        #pragma unroll
        for (int o = 16; o; o >>= 1) s += __shfl_xor_sync(0xffffffffu, s, o);
        float inv = 1.f / s;
        sc[w][lane]      = v0 * inv;
        sc[w][lane + 32] = v1 * inv;
        sc[w][lane + 64] = v2 * inv;
        sc[w][lane + 96] = v3 * inv;
    }
    __syncthreads();

    // ---- attn @ V: register accumulation over this warp's keys ----
    float acc[8];
    #pragma unroll
    for (int j = 0; j < 8; j++) acc[j] = 0.f;

    #pragma unroll
    for (int jt = 0; jt < 4; jt++) {
        #pragma unroll
        for (int i = 0; i < 4; i++) {
            int kk = jt * 32 + w * 8 + i * 2 + (lane >> 4);
            int gi = idx_s[kk];
            uint4 vv = *(const uint4*)(g_vh + (size_t)gi * C + dslot * 8);
            const __half2* vp = (const __half2*)&vv;
            float p = sc[hl][kk];
            #pragma unroll
            for (int q2 = 0; q2 < 4; q2++) {
                float2 f = __half22float2(vp[q2]);
                acc[q2 * 2]     = fmaf(p, f.x, acc[q2 * 2]);
                acc[q2 * 2 + 1] = fmaf(p, f.y, acc[q2 * 2 + 1]);
            }
        }
    }
    #pragma unroll
    for (int j = 0; j < 8; j++) acc[j] += __shfl_xor_sync(0xffffffffu, acc[j], 16);
    if (lane < 16) {
        #pragma unroll
        for (int j = 0; j < 8; j++) part[w][dslot * 8 + j] = acc[j];
    }
    __syncthreads();

    float o = part[0][tid] + part[1][tid] + part[2][tid] + part[3][tid];
    o *= g_g[(size_t)l * C + tid];
    out_ao[(size_t)l * C + tid] = o;
}

// ---------------------------------------------------------------------------
extern "C" void kernel_launch(void* const* d_in, const int* in_sizes, int n_in,
                              void* d_out, int out_size) {
    const float* Q_L     = (const float*)d_in[0];
    const float* P_LL    = (const float*)d_in[1];
    const int*   indices = (const int*)d_in[2];
    const float* Wq      = (const float*)d_in[3];
    const float* Wk      = (const float*)d_in[4];
    const float* Wv      = (const float*)d_in[5];
    const float* Wg      = (const float*)d_in[6];
    const float* Wb      = (const float*)d_in[7];
    const float* Wo      = (const float*)d_in[8];
    const float* ln1_w   = (const float*)d_in[9];
    const float* lnq_w   = (const float*)d_in[10];
    const float* lnk_w   = (const float*)d_in[11];
    float* out = (float*)d_out;

    float *a, *q, *k, *v, *g, *ao;
    cudaGetSymbolAddress((void**)&a,  g_a);
    cudaGetSymbolAddress((void**)&q,  g_q);
    cudaGetSymbolAddress((void**)&k,  g_k);
    cudaGetSymbolAddress((void**)&v,  g_v);
    cudaGetSymbolAddress((void**)&g,  g_g);
    cudaGetSymbolAddress((void**)&ao, g_ao);

    // 1) a = RMSNorm(Q_L, ln1_w)
    rms8_kernel<<<L / 8, 256>>>(Q_L, ln1_w, a);

    // 2) fused q/k/v/g projections, tf32 tensor cores (sigmoid on g)
    gemm_tf32_kernel<4, 2, 2, 4><<<dim3(L / 128, 8), 256>>>(
        a, Wq, Wk, Wv, Wg, q, k, v, g, /*sigmoidMat=*/3);

    // 3) q-rms (fp32), k-rms -> fp16, v -> fp16
    postproc_kernel<<<L / 8, 256>>>(lnq_w, lnk_w);

    // 4) attention with gathered pair bias + gate
    attn_kernel<<<L, 128>>>(P_LL, indices, Wb, ao);

    // 5) output projection, tf32 tensor cores
    gemm_tf32_kernel<2, 4, 2, 2><<<dim3(L / 64, 2), 256>>>(
        ao, Wo, Wo, Wo, Wo, out, out, out, out, /*sigmoidMat=*/-1);
}